// round 1
// baseline (speedup 1.0000x reference)
#include <cuda_runtime.h>
#include <cuda_bf16.h>

// Problem constants (fixed by the reference setup)
#define B_WIN   4096
#define SEQ     49
#define CDIM    192
#define NHEAD   6
#define HDIM    32
#define KD      192        // inner K for both GEMMs
#define QKV_COLS 576
#define NWIN    64

// Scratch (allocation-free rule: static __device__ arrays)
__device__ float g_qkv [(size_t)B_WIN * SEQ * QKV_COLS];   // (B_, N, 3C)
__device__ float g_attn[(size_t)B_WIN * SEQ * CDIM];       // (B_, N, C) attention output
__device__ float g_bias[NHEAD * SEQ * SEQ];                // (h, n, m) rel-pos bias

// ---------------------------------------------------------------------------
// K0: gather relative-position bias: g_bias[h][n][m] = table[rel_index[n,m]][h]
// ---------------------------------------------------------------------------
__global__ void bias_kernel(const float* __restrict__ table,
                            const int* __restrict__ rel_index)
{
    int i = blockIdx.x * blockDim.x + threadIdx.x;
    if (i < SEQ * SEQ) {
        int r = rel_index[i];
        #pragma unroll
        for (int h = 0; h < NHEAD; ++h)
            g_bias[h * SEQ * SEQ + i] = table[r * NHEAD + h];
    }
}

// ---------------------------------------------------------------------------
// K1/K3: SGEMM  out[m][n] = sum_k A[m][k] * W[n][k] + bias[n]
//   PHASE1: A = Ain (x),      out = g_qkv,  epilogue scales q columns (<192)
//   !PHASE1: A = g_attn,      out = Oin (d_out)
// Tiles: 64x64, K-tile 32, 256 threads, 4x4 micro-tile, transposed smem.
// M = 200704 (divisible by 64), N in {576,192} (divisible by 64): no guards.
// ---------------------------------------------------------------------------
template<bool PHASE1>
__global__ void __launch_bounds__(256)
gemm_kernel(const float* __restrict__ Ain, const float* __restrict__ W,
            const float* __restrict__ bias, float* __restrict__ Oin,
            int Ncols, float qscale)
{
    __shared__ __align__(16) float As[32][64];
    __shared__ __align__(16) float Bs[32][64];

    const float* A = PHASE1 ? Ain : g_attn;
    float*       O = PHASE1 ? g_qkv : Oin;

    const int tid = threadIdx.x;
    const int tx  = tid & 15;
    const int ty  = tid >> 4;
    const size_t m0 = (size_t)blockIdx.x * 64;
    const int    n0 = blockIdx.y * 64;

    float acc[4][4] = {};

    for (int kt = 0; kt < KD; kt += 32) {
        // Load 64x32 tiles of A and W, transposed to [k][row] in smem.
        #pragma unroll
        for (int i = 0; i < 2; ++i) {
            int idx = tid + i * 256;        // 0..511
            int r   = idx >> 3;             // 0..63
            int kq  = idx & 7;              // float4 index within 32 k's
            float4 va = *(const float4*)(A + (m0 + r) * KD + kt + kq * 4);
            As[kq*4+0][r] = va.x;
            As[kq*4+1][r] = va.y;
            As[kq*4+2][r] = va.z;
            As[kq*4+3][r] = va.w;
            float4 vb = *(const float4*)(W + (size_t)(n0 + r) * KD + kt + kq * 4);
            Bs[kq*4+0][r] = vb.x;
            Bs[kq*4+1][r] = vb.y;
            Bs[kq*4+2][r] = vb.z;
            Bs[kq*4+3][r] = vb.w;
        }
        __syncthreads();

        #pragma unroll
        for (int k = 0; k < 32; ++k) {
            float4 a4 = *(const float4*)&As[k][ty * 4];
            float4 b4 = *(const float4*)&Bs[k][tx * 4];
            float av[4] = {a4.x, a4.y, a4.z, a4.w};
            float bv[4] = {b4.x, b4.y, b4.z, b4.w};
            #pragma unroll
            for (int i = 0; i < 4; ++i)
                #pragma unroll
                for (int j = 0; j < 4; ++j)
                    acc[i][j] += av[i] * bv[j];
        }
        __syncthreads();
    }

    const int colbase = n0 + tx * 4;
    float4 bv4 = *(const float4*)(bias + colbase);
    const float bb[4] = {bv4.x, bv4.y, bv4.z, bv4.w};
    // q columns are [0,192); colbase is 4-aligned and 192 % 4 == 0 so the
    // whole float4 is on one side of the boundary.
    const bool do_scale = PHASE1 && (colbase < CDIM);

    #pragma unroll
    for (int i = 0; i < 4; ++i) {
        size_t row = m0 + ty * 4 + i;
        float v0 = acc[i][0] + bb[0];
        float v1 = acc[i][1] + bb[1];
        float v2 = acc[i][2] + bb[2];
        float v3 = acc[i][3] + bb[3];
        if (do_scale) { v0 *= qscale; v1 *= qscale; v2 *= qscale; v3 *= qscale; }
        float4 o = make_float4(v0, v1, v2, v3);
        *(float4*)(O + row * (size_t)Ncols + colbase) = o;
    }
}

// ---------------------------------------------------------------------------
// K2: per-(window, head) attention.
//   blockIdx.x = window b (0..4095), blockIdx.y = head h (0..5), 128 threads.
//   S = q k^T + bias[h] + mask[b%64]; softmax rows; O = S v -> g_attn.
// ---------------------------------------------------------------------------
__global__ void __launch_bounds__(128)
attn_kernel(const float* __restrict__ mask)
{
    // Padded to 36 floats/row: rows stay 16B-aligned, banks spread (4m mod 32).
    __shared__ __align__(16) float sq[SEQ][36];
    __shared__ __align__(16) float sk[SEQ][36];
    __shared__ __align__(16) float sv[SEQ][36];
    __shared__ float Ss[SEQ][50];

    const int b   = blockIdx.x;
    const int h   = blockIdx.y;
    const int tid = threadIdx.x;

    const float* base = g_qkv + (size_t)b * SEQ * QKV_COLS;

    // Load q, k, v tiles (49 x 32 each) as float4.
    for (int idx = tid; idx < SEQ * 8; idx += 128) {
        int n  = idx >> 3;
        int dq = (idx & 7) * 4;
        *(float4*)&sq[n][dq] = *(const float4*)(base + n * QKV_COLS + h * HDIM + dq);
        *(float4*)&sk[n][dq] = *(const float4*)(base + n * QKV_COLS + CDIM + h * HDIM + dq);
        *(float4*)&sv[n][dq] = *(const float4*)(base + n * QKV_COLS + 2 * CDIM + h * HDIM + dq);
    }
    __syncthreads();

    const float* bptr = g_bias + h * SEQ * SEQ;
    const float* mptr = mask + (size_t)(b & (NWIN - 1)) * SEQ * SEQ;

    // Scores S[n][m] = q[n] . k[m] + bias + mask
    for (int idx = tid; idx < SEQ * SEQ; idx += 128) {
        int n = idx / SEQ;
        int m = idx % SEQ;
        float s = 0.0f;
        #pragma unroll
        for (int d4 = 0; d4 < 8; ++d4) {
            float4 a  = *(const float4*)&sq[n][d4 * 4];
            float4 bk = *(const float4*)&sk[m][d4 * 4];
            s += a.x * bk.x + a.y * bk.y + a.z * bk.z + a.w * bk.w;
        }
        Ss[n][m] = s + bptr[idx] + mptr[idx];
    }
    __syncthreads();

    // Row softmax (one thread per row).
    if (tid < SEQ) {
        float mx = -1e30f;
        #pragma unroll 7
        for (int m = 0; m < SEQ; ++m) mx = fmaxf(mx, Ss[tid][m]);
        float sum = 0.0f;
        #pragma unroll 7
        for (int m = 0; m < SEQ; ++m) {
            float e = expf(Ss[tid][m] - mx);
            Ss[tid][m] = e;
            sum += e;
        }
        float inv = 1.0f / sum;
        #pragma unroll 7
        for (int m = 0; m < SEQ; ++m) Ss[tid][m] *= inv;
    }
    __syncthreads();

    // O[n][d] = sum_m S[n][m] * v[m][d]  -> g_attn[b][n][h*32+d]
    float* obase = g_attn + (size_t)b * SEQ * CDIM + h * HDIM;
    for (int idx = tid; idx < SEQ * HDIM; idx += 128) {
        int n = idx >> 5;
        int d = idx & 31;
        float s = 0.0f;
        #pragma unroll 7
        for (int m = 0; m < SEQ; ++m) s += Ss[n][m] * sv[m][d];
        obase[n * CDIM + d] = s;
    }
}

// ---------------------------------------------------------------------------
// Launch: bias gather -> QKV GEMM (q scaled) -> attention -> proj GEMM
// ---------------------------------------------------------------------------
extern "C" void kernel_launch(void* const* d_in, const int* in_sizes, int n_in,
                              void* d_out, int out_size)
{
    const float* x     = (const float*)d_in[0];
    const float* mask  = (const float*)d_in[1];
    const float* table = (const float*)d_in[2];
    const float* qkvw  = (const float*)d_in[3];
    const float* qkvb  = (const float*)d_in[4];
    const float* projw = (const float*)d_in[5];
    const float* projb = (const float*)d_in[6];
    const int*   relix = (const int*)d_in[7];
    float* out = (float*)d_out;

    const float qscale = 0.17677669529663687f;  // 1/sqrt(32)

    bias_kernel<<<(SEQ * SEQ + 255) / 256, 256>>>(table, relix);

    // QKV: M=200704, N=576, K=192
    gemm_kernel<true><<<dim3(200704 / 64, QKV_COLS / 64), 256>>>(
        x, qkvw, qkvb, nullptr, QKV_COLS, qscale);

    // Attention per (window, head)
    attn_kernel<<<dim3(B_WIN, NHEAD), 128>>>(mask);

    // Proj: M=200704, N=192, K=192
    gemm_kernel<false><<<dim3(200704 / 64, CDIM / 64), 256>>>(
        nullptr, projw, projb, out, CDIM, 1.0f);
}

// round 3
// speedup vs baseline: 2.3012x; 2.3012x over previous
#include <cuda_runtime.h>
#include <cstdint>

// ---------------- problem constants ----------------
#define B_WIN    4096
#define SEQ      49
#define CDIM     192
#define NHEAD    6
#define HDIM     32
#define KD       192
#define QKV_COLS 576
#define MROWS    200704       // B_WIN * SEQ

// ---------------- scratch (__device__ globals, allocation-free) -------------
__device__ float g_qkv [(size_t)B_WIN * SEQ * QKV_COLS];
__device__ float g_attn[(size_t)B_WIN * SEQ * CDIM];
__device__ float g_bias[NHEAD * SEQ * SEQ];

__device__ __forceinline__ uint32_t f2tf32(float x) {
    uint32_t r; asm("cvt.rna.tf32.f32 %0, %1;" : "=r"(r) : "f"(x)); return r;
}

__device__ __forceinline__ void mma_tf32(float* d, const uint32_t* a, const uint32_t* b) {
    asm volatile(
        "mma.sync.aligned.m16n8k8.row.col.f32.tf32.tf32.f32 "
        "{%0,%1,%2,%3}, {%4,%5,%6,%7}, {%8,%9}, {%0,%1,%2,%3};"
        : "+f"(d[0]), "+f"(d[1]), "+f"(d[2]), "+f"(d[3])
        : "r"(a[0]), "r"(a[1]), "r"(a[2]), "r"(a[3]), "r"(b[0]), "r"(b[1]));
}

// ---------------------------------------------------------------------------
// K0: gather relative-position bias: g_bias[h][n][m] = table[rel_index[n,m]][h]
// ---------------------------------------------------------------------------
__global__ void bias_kernel(const float* __restrict__ table,
                            const int* __restrict__ rel_index)
{
    int i = blockIdx.x * blockDim.x + threadIdx.x;
    if (i < SEQ * SEQ) {
        int r = rel_index[i];
        #pragma unroll
        for (int h = 0; h < NHEAD; ++h)
            g_bias[h * SEQ * SEQ + i] = table[r * NHEAD + h];
    }
}

// ---------------------------------------------------------------------------
// tf32 HMMA GEMM: out[m][n] = sum_k A[m][k]*W[n][k] + bias[n]
//   Tile 128x96, BK=32, 256 thr = 8 warps (4M x 2N), warp tile 32x48.
//   Double-buffered SMEM (stride 36), register-staged prefetch,
//   cvt.rna.tf32 at STS. Epilogue staged via SMEM for coalesced STG.
//   PHASE1: A = x, O = g_qkv (scale q cols: n0 < 192).  !PHASE1: A=g_attn, O=Oin.
// ---------------------------------------------------------------------------
#define ABUF 4608u             // 128*36 floats
#define BBUF 3456u             // 96*36 floats
#define GEMM_SMEM_FLOATS (2u*ABUF + 2u*BBUF)   // 16128 floats = 64512 B

template<bool PHASE1>
__global__ void __launch_bounds__(256, 2)
gemm_mma(const float* __restrict__ Ain, const float* __restrict__ W,
         const float* __restrict__ bias, float* __restrict__ Oin,
         int Ncols, float qscale)
{
    extern __shared__ float sm[];
    float* As[2] = { sm,              sm + ABUF };
    float* Bs[2] = { sm + 2 * ABUF,   sm + 2 * ABUF + BBUF };
    __shared__ float bias_s[96];

    const float* A = PHASE1 ? Ain : g_attn;
    float*       O = PHASE1 ? g_qkv : Oin;

    const int tid  = threadIdx.x;
    const int wid  = tid >> 5;
    const int lane = tid & 31;
    const int gid  = lane >> 2;         // 0..7
    const int tig  = lane & 3;          // 0..3
    const size_t m0 = (size_t)blockIdx.x * 128;
    const int    n0 = blockIdx.y * 96;
    const int    wm = (wid >> 1) * 32;  // warp M offset
    const int    wn = (wid & 1) * 48;   // warp N offset

    if (tid < 24) ((float4*)bias_s)[tid] = ((const float4*)(bias + n0))[tid];

    // per-thread global-load coords (fixed across k-tiles)
    const int ar = (tid * 4 + 0) >> 3;  // dummy init; real pattern below
    (void)ar;

    float4 pa[4], pb[3];

    auto ldg_tile = [&](int kt) {
        const int k0 = kt * 32;
        #pragma unroll
        for (int i = 0; i < 4; ++i) {
            int idx = tid + i * 256;            // 0..1023
            int r = idx >> 3, q = idx & 7;
            pa[i] = *(const float4*)(A + (m0 + r) * (size_t)KD + k0 + q * 4);
        }
        #pragma unroll
        for (int i = 0; i < 3; ++i) {
            int idx = tid + i * 256;            // 0..767
            int r = idx >> 3, q = idx & 7;
            pb[i] = *(const float4*)(W + (size_t)(n0 + r) * KD + k0 + q * 4);
        }
    };
    auto sts_tile = [&](int buf) {
        #pragma unroll
        for (int i = 0; i < 4; ++i) {
            int idx = tid + i * 256;
            int r = idx >> 3, q = idx & 7;
            uint4 t = make_uint4(f2tf32(pa[i].x), f2tf32(pa[i].y),
                                 f2tf32(pa[i].z), f2tf32(pa[i].w));
            *(uint4*)(As[buf] + r * 36 + q * 4) = t;
        }
        #pragma unroll
        for (int i = 0; i < 3; ++i) {
            int idx = tid + i * 256;
            int r = idx >> 3, q = idx & 7;
            uint4 t = make_uint4(f2tf32(pb[i].x), f2tf32(pb[i].y),
                                 f2tf32(pb[i].z), f2tf32(pb[i].w));
            *(uint4*)(Bs[buf] + r * 36 + q * 4) = t;
        }
    };

    float acc[2][6][4] = {};

    ldg_tile(0);
    sts_tile(0);
    __syncthreads();

    #pragma unroll 1
    for (int kt = 0; kt < 6; ++kt) {
        const int buf = kt & 1;
        if (kt < 5) ldg_tile(kt + 1);

        const uint32_t* Au = (const uint32_t*)As[buf];
        const uint32_t* Bu = (const uint32_t*)Bs[buf];
        #pragma unroll
        for (int kk = 0; kk < 32; kk += 8) {
            uint32_t afr[2][4], bfr[6][2];
            #pragma unroll
            for (int mi = 0; mi < 2; ++mi) {
                int r = wm + mi * 16 + gid;
                afr[mi][0] = Au[r * 36 + kk + tig];
                afr[mi][1] = Au[(r + 8) * 36 + kk + tig];
                afr[mi][2] = Au[r * 36 + kk + 4 + tig];
                afr[mi][3] = Au[(r + 8) * 36 + kk + 4 + tig];
            }
            #pragma unroll
            for (int ni = 0; ni < 6; ++ni) {
                int r = wn + ni * 8 + gid;
                bfr[ni][0] = Bu[r * 36 + kk + tig];
                bfr[ni][1] = Bu[r * 36 + kk + 4 + tig];
            }
            #pragma unroll
            for (int mi = 0; mi < 2; ++mi)
                #pragma unroll
                for (int ni = 0; ni < 6; ++ni)
                    mma_tf32(acc[mi][ni], afr[mi], bfr[ni]);
        }
        __syncthreads();
        if (kt < 5) {
            sts_tile(buf ^ 1);
            __syncthreads();
        }
    }

    // ---- epilogue: stage to SMEM (stride 100), then coalesced STG ----
    float* stage = sm;                 // 128*100 = 12800 floats <= 16128
    #pragma unroll
    for (int mi = 0; mi < 2; ++mi) {
        int row0 = wm + mi * 16 + gid;
        #pragma unroll
        for (int ni = 0; ni < 6; ++ni) {
            int col0 = wn + ni * 8 + 2 * tig;
            *(float2*)(stage + row0 * 100 + col0)       = make_float2(acc[mi][ni][0], acc[mi][ni][1]);
            *(float2*)(stage + (row0 + 8) * 100 + col0) = make_float2(acc[mi][ni][2], acc[mi][ni][3]);
        }
    }
    __syncthreads();

    const bool doscale = PHASE1 && (n0 < CDIM);
    #pragma unroll
    for (int i = 0; i < 12; ++i) {     // 128*96/4 = 3072 float4
        int idx = tid + i * 256;
        int row = idx / 24, c4 = idx - row * 24;
        float4 v  = *(float4*)(stage + row * 100 + c4 * 4);
        float4 bv = *(float4*)(bias_s + c4 * 4);
        float4 o;
        o.x = v.x + bv.x; o.y = v.y + bv.y; o.z = v.z + bv.z; o.w = v.w + bv.w;
        if (doscale) { o.x *= qscale; o.y *= qscale; o.z *= qscale; o.w *= qscale; }
        *(float4*)(O + (m0 + row) * (size_t)Ncols + n0 + c4 * 4) = o;
    }
}

// ---------------------------------------------------------------------------
// K2: attention, one block per window (all 6 heads), 384 threads.
// Thread owns score row n of head h; k/v in SMEM (broadcast LDS),
// q + output accumulators in registers, scores in private SMEM row.
// ---------------------------------------------------------------------------
#define ATTN_SMEM_BYTES (6*49*32*4 * 2 + 6*49*51*4)

__global__ void __launch_bounds__(384)
attn_kernel(const float* __restrict__ mask)
{
    extern __shared__ float smn[];
    float* sk = smn;                      // [6][49][32]
    float* sv = smn + 6 * 49 * 32;        // [6][49][32]
    float* Ss = sv + 6 * 49 * 32;         // [6][49][51]

    const int b   = blockIdx.x;
    const int tid = threadIdx.x;
    const float* base = g_qkv + (size_t)b * SEQ * QKV_COLS;

    for (int i = tid; i < 6 * 49 * 8; i += 384) {
        int h = i / 392; int rem = i - h * 392;
        int n = rem >> 3; int q = rem & 7;
        const float* src = base + n * QKV_COLS + CDIM + h * HDIM + q * 4;
        *(float4*)(sk + (h * 49 + n) * 32 + q * 4) = *(const float4*)src;
        *(float4*)(sv + (h * 49 + n) * 32 + q * 4) = *(const float4*)(src + CDIM);
    }
    __syncthreads();

    const int wid = tid >> 5;
    const int h   = wid >> 1;
    const int n   = (wid & 1) * 32 + (tid & 31);
    if (n < SEQ) {
        const float4* qp = (const float4*)(base + n * QKV_COLS + h * HDIM);
        float4 qv[8];
        #pragma unroll
        for (int d = 0; d < 8; ++d) qv[d] = qp[d];

        float* srow = Ss + (h * 49 + n) * 51;
        const float* kh = sk + h * 49 * 32;

        for (int m = 0; m < SEQ; ++m) {
            const float4* kp = (const float4*)(kh + m * 32);
            float s = 0.f;
            #pragma unroll
            for (int d = 0; d < 8; ++d) {
                float4 kv = kp[d];
                s += qv[d].x * kv.x + qv[d].y * kv.y + qv[d].z * kv.z + qv[d].w * kv.w;
            }
            srow[m] = s;
        }

        const float* bp = g_bias + h * SEQ * SEQ + n * SEQ;
        const float* mp = mask + (size_t)(b & 63) * SEQ * SEQ + n * SEQ;
        float mx = -1e30f;
        for (int m = 0; m < SEQ; ++m) {
            float s = srow[m] + bp[m] + mp[m];
            srow[m] = s;
            mx = fmaxf(mx, s);
        }
        float sum = 0.f;
        for (int m = 0; m < SEQ; ++m) {
            float e = __expf(srow[m] - mx);
            srow[m] = e;
            sum += e;
        }
        float inv = 1.0f / sum;

        float4 accv[8] = {};
        const float* vh = sv + h * 49 * 32;
        for (int m = 0; m < SEQ; ++m) {
            float p = srow[m];
            const float4* vp = (const float4*)(vh + m * 32);
            #pragma unroll
            for (int d = 0; d < 8; ++d) {
                float4 vv = vp[d];
                accv[d].x += p * vv.x; accv[d].y += p * vv.y;
                accv[d].z += p * vv.z; accv[d].w += p * vv.w;
            }
        }
        float4* op = (float4*)(g_attn + (size_t)b * SEQ * CDIM + n * CDIM + h * HDIM);
        #pragma unroll
        for (int d = 0; d < 8; ++d) {
            accv[d].x *= inv; accv[d].y *= inv; accv[d].z *= inv; accv[d].w *= inv;
            op[d] = accv[d];
        }
    }
}

// ---------------------------------------------------------------------------
extern "C" void kernel_launch(void* const* d_in, const int* in_sizes, int n_in,
                              void* d_out, int out_size)
{
    const float* x     = (const float*)d_in[0];
    const float* mask  = (const float*)d_in[1];
    const float* table = (const float*)d_in[2];
    const float* qkvw  = (const float*)d_in[3];
    const float* qkvb  = (const float*)d_in[4];
    const float* projw = (const float*)d_in[5];
    const float* projb = (const float*)d_in[6];
    const int*   relix = (const int*)d_in[7];
    float* out = (float*)d_out;

    const float qscale = 0.17677669529663687f;  // 1/sqrt(32)
    const int gemm_smem = GEMM_SMEM_FLOATS * 4;

    cudaFuncSetAttribute((void*)gemm_mma<true>,
                         cudaFuncAttributeMaxDynamicSharedMemorySize, gemm_smem);
    cudaFuncSetAttribute((void*)gemm_mma<false>,
                         cudaFuncAttributeMaxDynamicSharedMemorySize, gemm_smem);
    cudaFuncSetAttribute((void*)attn_kernel,
                         cudaFuncAttributeMaxDynamicSharedMemorySize, ATTN_SMEM_BYTES);

    bias_kernel<<<(SEQ * SEQ + 255) / 256, 256>>>(table, relix);

    // QKV: M=200704, N=576 (6 tiles of 96), K=192
    gemm_mma<true><<<dim3(MROWS / 128, 6), 256, gemm_smem>>>(
        x, qkvw, qkvb, nullptr, QKV_COLS, qscale);

    attn_kernel<<<B_WIN, 384, ATTN_SMEM_BYTES>>>(mask);

    // Proj: M=200704, N=192 (2 tiles of 96), K=192
    gemm_mma<false><<<dim3(MROWS / 128, 2), 256, gemm_smem>>>(
        nullptr, projw, projb, out, CDIM, 1.0f);
}

// round 4
// speedup vs baseline: 2.9938x; 1.3010x over previous
#include <cuda_runtime.h>
#include <cstdint>

// ---------------- problem constants ----------------
#define B_WIN    4096
#define SEQ      49
#define CDIM     192
#define NHEAD    6
#define HDIM     32
#define KD       192
#define QKV_COLS 576
#define MROWS    200704       // B_WIN * SEQ

// ---------------- scratch (__device__ globals, allocation-free) -------------
__device__ float g_qkv [(size_t)B_WIN * SEQ * QKV_COLS];
__device__ float g_attn[(size_t)B_WIN * SEQ * CDIM];
__device__ float g_bm  [64 * NHEAD * SEQ * 56];   // fused bias+mask, cols padded to 56

__device__ __forceinline__ uint32_t f2tf32(float x) {
    uint32_t r; asm("cvt.rna.tf32.f32 %0, %1;" : "=r"(r) : "f"(x)); return r;
}
__device__ __forceinline__ void split2(float v, float& hi, float& lo) {
    hi = __uint_as_float(f2tf32(v));
    lo = __uint_as_float(f2tf32(v - hi));
}

__device__ __forceinline__ void mma_tf32(float* d, const uint32_t* a, const uint32_t* b) {
    asm volatile(
        "mma.sync.aligned.m16n8k8.row.col.f32.tf32.tf32.f32 "
        "{%0,%1,%2,%3}, {%4,%5,%6,%7}, {%8,%9}, {%0,%1,%2,%3};"
        : "+f"(d[0]), "+f"(d[1]), "+f"(d[2]), "+f"(d[3])
        : "r"(a[0]), "r"(a[1]), "r"(a[2]), "r"(a[3]), "r"(b[0]), "r"(b[1]));
}
__device__ __forceinline__ void mma_f(float* d, float a0, float a1, float a2, float a3,
                                      float b0, float b1) {
    asm volatile(
        "mma.sync.aligned.m16n8k8.row.col.f32.tf32.tf32.f32 "
        "{%0,%1,%2,%3}, {%4,%5,%6,%7}, {%8,%9}, {%0,%1,%2,%3};"
        : "+f"(d[0]), "+f"(d[1]), "+f"(d[2]), "+f"(d[3])
        : "r"(__float_as_uint(a0)), "r"(__float_as_uint(a1)),
          "r"(__float_as_uint(a2)), "r"(__float_as_uint(a3)),
          "r"(__float_as_uint(b0)), "r"(__float_as_uint(b1)));
}

// ---------------------------------------------------------------------------
// K0: fused bias+mask table: g_bm[w][h][n][m] (m padded to 56 with -1e30)
// ---------------------------------------------------------------------------
__global__ void bm_kernel(const float* __restrict__ table,
                          const float* __restrict__ mask,
                          const int* __restrict__ rel_index)
{
    int i = blockIdx.x * blockDim.x + threadIdx.x;
    if (i >= 64 * NHEAD * SEQ * 56) return;
    int m = i % 56; int t = i / 56;
    int n = t % SEQ; t /= SEQ;
    int h = t % NHEAD; int w = t / NHEAD;
    float v = -1e30f;
    if (m < SEQ)
        v = table[rel_index[n * SEQ + m] * NHEAD + h]
          + mask[((size_t)w * SEQ + n) * SEQ + m];
    g_bm[i] = v;
}

// ---------------------------------------------------------------------------
// tf32 HMMA GEMM: out[m][n] = sum_k A[m][k]*W[n][k] + bias[n]
//   Tile 128x96, BK=32, 256 thr = 8 warps (4M x 2N), warp tile 32x48.
//   Double-buffered SMEM (stride 36), single __syncthreads per k-tile.
//   PHASE1: A = x, O = g_qkv (scale q cols: n0 < 192).  !PHASE1: A=g_attn, O=Oin.
// ---------------------------------------------------------------------------
#define ABUF 4608u             // 128*36 floats
#define BBUF 3456u             // 96*36 floats
#define GEMM_SMEM_FLOATS (2u*ABUF + 2u*BBUF)   // 16128 floats = 64512 B

template<bool PHASE1>
__global__ void __launch_bounds__(256, 2)
gemm_mma(const float* __restrict__ Ain, const float* __restrict__ W,
         const float* __restrict__ bias, float* __restrict__ Oin,
         int Ncols, float qscale)
{
    extern __shared__ float sm[];
    float* As[2] = { sm,              sm + ABUF };
    float* Bs[2] = { sm + 2 * ABUF,   sm + 2 * ABUF + BBUF };
    __shared__ float bias_s[96];

    const float* A = PHASE1 ? Ain : g_attn;
    float*       O = PHASE1 ? g_qkv : Oin;

    const int tid  = threadIdx.x;
    const int wid  = tid >> 5;
    const int lane = tid & 31;
    const int gid  = lane >> 2;
    const int tig  = lane & 3;
    const size_t m0 = (size_t)blockIdx.x * 128;
    const int    n0 = blockIdx.y * 96;
    const int    wm = (wid >> 1) * 32;
    const int    wn = (wid & 1) * 48;

    if (tid < 24) ((float4*)bias_s)[tid] = ((const float4*)(bias + n0))[tid];

    float4 pa[4], pb[3];

    auto ldg_tile = [&](int kt) {
        const int k0 = kt * 32;
        #pragma unroll
        for (int i = 0; i < 4; ++i) {
            int idx = tid + i * 256;
            int r = idx >> 3, q = idx & 7;
            pa[i] = *(const float4*)(A + (m0 + r) * (size_t)KD + k0 + q * 4);
        }
        #pragma unroll
        for (int i = 0; i < 3; ++i) {
            int idx = tid + i * 256;
            int r = idx >> 3, q = idx & 7;
            pb[i] = *(const float4*)(W + (size_t)(n0 + r) * KD + k0 + q * 4);
        }
    };
    auto sts_tile = [&](int buf) {
        #pragma unroll
        for (int i = 0; i < 4; ++i) {
            int idx = tid + i * 256;
            int r = idx >> 3, q = idx & 7;
            uint4 t = make_uint4(f2tf32(pa[i].x), f2tf32(pa[i].y),
                                 f2tf32(pa[i].z), f2tf32(pa[i].w));
            *(uint4*)(As[buf] + r * 36 + q * 4) = t;
        }
        #pragma unroll
        for (int i = 0; i < 3; ++i) {
            int idx = tid + i * 256;
            int r = idx >> 3, q = idx & 7;
            uint4 t = make_uint4(f2tf32(pb[i].x), f2tf32(pb[i].y),
                                 f2tf32(pb[i].z), f2tf32(pb[i].w));
            *(uint4*)(Bs[buf] + r * 36 + q * 4) = t;
        }
    };

    float acc[2][6][4] = {};

    ldg_tile(0);
    sts_tile(0);
    __syncthreads();

    #pragma unroll 1
    for (int kt = 0; kt < 6; ++kt) {
        const int buf = kt & 1;
        if (kt < 5) ldg_tile(kt + 1);

        const uint32_t* Au = (const uint32_t*)As[buf];
        const uint32_t* Bu = (const uint32_t*)Bs[buf];
        #pragma unroll
        for (int kk = 0; kk < 32; kk += 8) {
            uint32_t afr[2][4], bfr[6][2];
            #pragma unroll
            for (int mi = 0; mi < 2; ++mi) {
                int r = wm + mi * 16 + gid;
                afr[mi][0] = Au[r * 36 + kk + tig];
                afr[mi][1] = Au[(r + 8) * 36 + kk + tig];
                afr[mi][2] = Au[r * 36 + kk + 4 + tig];
                afr[mi][3] = Au[(r + 8) * 36 + kk + 4 + tig];
            }
            #pragma unroll
            for (int ni = 0; ni < 6; ++ni) {
                int r = wn + ni * 8 + gid;
                bfr[ni][0] = Bu[r * 36 + kk + tig];
                bfr[ni][1] = Bu[r * 36 + kk + 4 + tig];
            }
            #pragma unroll
            for (int mi = 0; mi < 2; ++mi)
                #pragma unroll
                for (int ni = 0; ni < 6; ++ni)
                    mma_tf32(acc[mi][ni], afr[mi], bfr[ni]);
        }
        if (kt < 5) sts_tile(buf ^ 1);
        __syncthreads();
    }

    // ---- epilogue: stage to SMEM (stride 100), then coalesced STG ----
    float* stage = sm;
    #pragma unroll
    for (int mi = 0; mi < 2; ++mi) {
        int row0 = wm + mi * 16 + gid;
        #pragma unroll
        for (int ni = 0; ni < 6; ++ni) {
            int col0 = wn + ni * 8 + 2 * tig;
            *(float2*)(stage + row0 * 100 + col0)       = make_float2(acc[mi][ni][0], acc[mi][ni][1]);
            *(float2*)(stage + (row0 + 8) * 100 + col0) = make_float2(acc[mi][ni][2], acc[mi][ni][3]);
        }
    }
    __syncthreads();

    const bool doscale = PHASE1 && (n0 < CDIM);
    #pragma unroll
    for (int i = 0; i < 12; ++i) {
        int idx = tid + i * 256;
        int row = idx / 24, c4 = idx - row * 24;
        float4 v  = *(float4*)(stage + row * 100 + c4 * 4);
        float4 bv = *(float4*)(bias_s + c4 * 4);
        float4 o;
        o.x = v.x + bv.x; o.y = v.y + bv.y; o.z = v.z + bv.z; o.w = v.w + bv.w;
        if (doscale) { o.x *= qscale; o.y *= qscale; o.z *= qscale; o.w *= qscale; }
        *(float4*)(O + (m0 + row) * (size_t)Ncols + n0 + c4 * 4) = o;
    }
}

// ---------------------------------------------------------------------------
// K2: tensor-core attention. One block per (window, head), 128 thr / 4 warps.
// Warp w owns rows [w*16, w*16+16). 3xTF32 split MMAs for QK^T and P@V.
// Softmax in registers via quad shuffles; P fragments via intra-quad shfl.
// SMEM hi/lo arrays, strides chosen conflict-free for both access patterns.
// ---------------------------------------------------------------------------
#define QSTR 36
#define KSTR 36
#define VSTR 40
#define ATTN_SMEM_FLOATS (2*49*QSTR + 2*56*KSTR + 2*56*VSTR)   // 12040 -> 48160 B

__global__ void __launch_bounds__(128)
attn_mma()
{
    extern __shared__ float s[];
    float* qh = s;
    float* ql = qh + 49 * QSTR;
    float* kh = ql + 49 * QSTR;
    float* kl = kh + 56 * KSTR;
    float* vh = kl + 56 * KSTR;
    float* vl = vh + 56 * VSTR;

    const int b = blockIdx.x;
    const int h = blockIdx.y;
    const int tid = threadIdx.x;
    const float* base = g_qkv + (size_t)b * SEQ * QKV_COLS;

    // ---- load q (49x32), k/v (56x32 zero-padded), split hi/lo ----
    for (int i = tid; i < 49 * 8; i += 128) {
        int n = i >> 3, c = (i & 7) * 4;
        float4 v = *(const float4*)(base + n * QKV_COLS + h * HDIM + c);
        float4 hi, lo;
        split2(v.x, hi.x, lo.x); split2(v.y, hi.y, lo.y);
        split2(v.z, hi.z, lo.z); split2(v.w, hi.w, lo.w);
        *(float4*)(qh + n * QSTR + c) = hi;
        *(float4*)(ql + n * QSTR + c) = lo;
    }
    for (int i = tid; i < 56 * 8; i += 128) {
        int n = i >> 3, c = (i & 7) * 4;
        float4 kv = make_float4(0.f, 0.f, 0.f, 0.f), vv = kv;
        if (n < SEQ) {
            const float* src = base + n * QKV_COLS + CDIM + h * HDIM + c;
            kv = *(const float4*)src;
            vv = *(const float4*)(src + CDIM);
        }
        float4 hi, lo;
        split2(kv.x, hi.x, lo.x); split2(kv.y, hi.y, lo.y);
        split2(kv.z, hi.z, lo.z); split2(kv.w, hi.w, lo.w);
        *(float4*)(kh + n * KSTR + c) = hi;
        *(float4*)(kl + n * KSTR + c) = lo;
        split2(vv.x, hi.x, lo.x); split2(vv.y, hi.y, lo.y);
        split2(vv.z, hi.z, lo.z); split2(vv.w, hi.w, lo.w);
        *(float4*)(vh + n * VSTR + c) = hi;
        *(float4*)(vl + n * VSTR + c) = lo;
    }
    __syncthreads();

    const int lane = tid & 31, w = tid >> 5;
    const int gid = lane >> 2, tig = lane & 3;
    const int row0 = w * 16 + gid, row1 = row0 + 8;
    const int r0c = min(row0, 48), r1c = min(row1, 48);

    // ---- S = Q K^T (3xtf32) ----
    float c[7][4] = {};
    #pragma unroll
    for (int ks = 0; ks < 4; ++ks) {
        const int dk = ks * 8;
        float a0h = qh[r0c * QSTR + dk + tig],     a0l = ql[r0c * QSTR + dk + tig];
        float a1h = qh[r1c * QSTR + dk + tig],     a1l = ql[r1c * QSTR + dk + tig];
        float a2h = qh[r0c * QSTR + dk + tig + 4], a2l = ql[r0c * QSTR + dk + tig + 4];
        float a3h = qh[r1c * QSTR + dk + tig + 4], a3l = ql[r1c * QSTR + dk + tig + 4];
        #pragma unroll
        for (int nt = 0; nt < 7; ++nt) {
            int kr = nt * 8 + gid;
            float b0h = kh[kr * KSTR + dk + tig],     b0l = kl[kr * KSTR + dk + tig];
            float b1h = kh[kr * KSTR + dk + tig + 4], b1l = kl[kr * KSTR + dk + tig + 4];
            mma_f(c[nt], a0h, a1h, a2h, a3h, b0h, b1h);
            mma_f(c[nt], a0h, a1h, a2h, a3h, b0l, b1l);
            mma_f(c[nt], a0l, a1l, a2l, a3l, b0h, b1h);
        }
    }

    // ---- add fused bias+mask ----
    const float* bmp = g_bm + ((size_t)((b & 63) * NHEAD + h)) * (SEQ * 56);
    #pragma unroll
    for (int nt = 0; nt < 7; ++nt) {
        float2 bm0 = *(const float2*)(bmp + r0c * 56 + nt * 8 + 2 * tig);
        float2 bm1 = *(const float2*)(bmp + r1c * 56 + nt * 8 + 2 * tig);
        c[nt][0] += bm0.x; c[nt][1] += bm0.y;
        c[nt][2] += bm1.x; c[nt][3] += bm1.y;
    }

    // ---- softmax (per-row, quad shuffles) ----
    float mx0 = -1e30f, mx1 = -1e30f;
    #pragma unroll
    for (int nt = 0; nt < 7; ++nt) {
        mx0 = fmaxf(mx0, fmaxf(c[nt][0], c[nt][1]));
        mx1 = fmaxf(mx1, fmaxf(c[nt][2], c[nt][3]));
    }
    mx0 = fmaxf(mx0, __shfl_xor_sync(0xffffffffu, mx0, 1));
    mx0 = fmaxf(mx0, __shfl_xor_sync(0xffffffffu, mx0, 2));
    mx1 = fmaxf(mx1, __shfl_xor_sync(0xffffffffu, mx1, 1));
    mx1 = fmaxf(mx1, __shfl_xor_sync(0xffffffffu, mx1, 2));

    float s0 = 0.f, s1 = 0.f;
    #pragma unroll
    for (int nt = 0; nt < 7; ++nt) {
        c[nt][0] = __expf(c[nt][0] - mx0); s0 += c[nt][0];
        c[nt][1] = __expf(c[nt][1] - mx0); s0 += c[nt][1];
        c[nt][2] = __expf(c[nt][2] - mx1); s1 += c[nt][2];
        c[nt][3] = __expf(c[nt][3] - mx1); s1 += c[nt][3];
    }
    s0 += __shfl_xor_sync(0xffffffffu, s0, 1);
    s0 += __shfl_xor_sync(0xffffffffu, s0, 2);
    s1 += __shfl_xor_sync(0xffffffffu, s1, 1);
    s1 += __shfl_xor_sync(0xffffffffu, s1, 2);
    const float inv0 = 1.0f / s0, inv1 = 1.0f / s1;

    // ---- O = P V (3xtf32); P fragments gathered via intra-quad shfl ----
    float o[4][4] = {};
    const int sA = (lane & ~3) | (tig >> 1);
    const int sB = sA + 2;
    const bool odd = tig & 1;
    #pragma unroll
    for (int j = 0; j < 7; ++j) {
        float t00 = __shfl_sync(0xffffffffu, c[j][0], sA);
        float t01 = __shfl_sync(0xffffffffu, c[j][1], sA);
        float t20 = __shfl_sync(0xffffffffu, c[j][0], sB);
        float t21 = __shfl_sync(0xffffffffu, c[j][1], sB);
        float t10 = __shfl_sync(0xffffffffu, c[j][2], sA);
        float t11 = __shfl_sync(0xffffffffu, c[j][3], sA);
        float t30 = __shfl_sync(0xffffffffu, c[j][2], sB);
        float t31 = __shfl_sync(0xffffffffu, c[j][3], sB);
        float a0 = odd ? t01 : t00;
        float a2 = odd ? t21 : t20;
        float a1 = odd ? t11 : t10;
        float a3 = odd ? t31 : t30;
        float a0h, a0l, a1h, a1l, a2h, a2l, a3h, a3l;
        split2(a0, a0h, a0l); split2(a1, a1h, a1l);
        split2(a2, a2h, a2l); split2(a3, a3h, a3l);
        const int vr0 = j * 8 + tig, vr1 = vr0 + 4;
        #pragma unroll
        for (int nd = 0; nd < 4; ++nd) {
            int col = nd * 8 + gid;
            float b0h = vh[vr0 * VSTR + col], b0l = vl[vr0 * VSTR + col];
            float b1h = vh[vr1 * VSTR + col], b1l = vl[vr1 * VSTR + col];
            mma_f(o[nd], a0h, a1h, a2h, a3h, b0h, b1h);
            mma_f(o[nd], a0h, a1h, a2h, a3h, b0l, b1l);
            mma_f(o[nd], a0l, a1l, a2l, a3l, b0h, b1h);
        }
    }

    // ---- write O (rows < 49 only), scaled by 1/rowsum ----
    float* ob = g_attn + (size_t)b * SEQ * CDIM + h * HDIM;
    if (row0 < SEQ) {
        #pragma unroll
        for (int nd = 0; nd < 4; ++nd)
            *(float2*)(ob + row0 * CDIM + nd * 8 + 2 * tig) =
                make_float2(o[nd][0] * inv0, o[nd][1] * inv0);
    }
    if (row1 < SEQ) {
        #pragma unroll
        for (int nd = 0; nd < 4; ++nd)
            *(float2*)(ob + row1 * CDIM + nd * 8 + 2 * tig) =
                make_float2(o[nd][2] * inv1, o[nd][3] * inv1);
    }
}

// ---------------------------------------------------------------------------
extern "C" void kernel_launch(void* const* d_in, const int* in_sizes, int n_in,
                              void* d_out, int out_size)
{
    const float* x     = (const float*)d_in[0];
    const float* mask  = (const float*)d_in[1];
    const float* table = (const float*)d_in[2];
    const float* qkvw  = (const float*)d_in[3];
    const float* qkvb  = (const float*)d_in[4];
    const float* projw = (const float*)d_in[5];
    const float* projb = (const float*)d_in[6];
    const int*   relix = (const int*)d_in[7];
    float* out = (float*)d_out;

    const float qscale = 0.17677669529663687f;  // 1/sqrt(32)
    const int gemm_smem = GEMM_SMEM_FLOATS * 4;
    const int attn_smem = ATTN_SMEM_FLOATS * 4;

    cudaFuncSetAttribute((void*)gemm_mma<true>,
                         cudaFuncAttributeMaxDynamicSharedMemorySize, gemm_smem);
    cudaFuncSetAttribute((void*)gemm_mma<false>,
                         cudaFuncAttributeMaxDynamicSharedMemorySize, gemm_smem);
    cudaFuncSetAttribute((void*)attn_mma,
                         cudaFuncAttributeMaxDynamicSharedMemorySize, attn_smem);

    bm_kernel<<<(64 * NHEAD * SEQ * 56 + 255) / 256, 256>>>(table, mask, relix);

    // QKV: M=200704, N=576 (6 tiles of 96), K=192
    gemm_mma<true><<<dim3(MROWS / 128, 6), 256, gemm_smem>>>(
        x, qkvw, qkvb, nullptr, QKV_COLS, qscale);

    attn_mma<<<dim3(B_WIN, NHEAD), 128, attn_smem>>>();

    // Proj: M=200704, N=192 (2 tiles of 96), K=192
    gemm_mma<false><<<dim3(MROWS / 128, 2), 256, gemm_smem>>>(
        nullptr, projw, projb, out, CDIM, 1.0f);
}